// round 10
// baseline (speedup 1.0000x reference)
#include <cuda_runtime.h>
#include <cstdint>

#define KW      512
#define KP      (KW / 2)      // k-pairs total
#define KSPLIT  8
#define KPB     (KP / KSPLIT) // k-pairs per block = 32
#define NPT     4             // points per thread
#define BLK     128           // threads per block
#define PPB     (BLK * NPT)   // points per point-group = 512

typedef unsigned long long u64;

// ---------- packed f32x2 helpers ----------
__device__ __forceinline__ u64 pk2(float lo, float hi) {
    u64 r;
    asm("mov.b64 %0, {%1, %2};" : "=l"(r) : "f"(lo), "f"(hi));
    return r;
}
__device__ __forceinline__ void upk2(u64 v, float& lo, float& hi) {
    asm("mov.b64 {%0, %1}, %2;" : "=f"(lo), "=f"(hi) : "l"(v));
}
__device__ __forceinline__ u64 fma2(u64 a, u64 b, u64 c) {
    u64 d;
    asm("fma.rn.f32x2 %0, %1, %2, %3;" : "=l"(d) : "l"(a), "l"(b), "l"(c));
    return d;
}
__device__ __forceinline__ u64 mul2(u64 a, u64 b) {
    u64 d;
    asm("mul.rn.f32x2 %0, %1, %2;" : "=l"(d) : "l"(a), "l"(b));
    return d;
}
__device__ __forceinline__ u64 add2(u64 a, u64 b) {
    u64 d;
    asm("add.rn.f32x2 %0, %1, %2;" : "=l"(d) : "l"(a), "l"(b));
    return d;
}
__device__ __forceinline__ float ex2f(float a) {
    float r;
    asm("ex2.approx.ftz.f32 %0, %1;" : "=f"(r) : "f"(a));
    return r;
}
__device__ __forceinline__ uint32_t smem_u32(const void* p) {
    uint32_t a;
    asm("{ .reg .u64 t; cvta.to.shared.u64 t, %1; cvt.u32.u64 %0, t; }"
        : "=r"(a) : "l"(p));
    return a;
}

// Per k-pair constants, 7 x 16B (layout per round-3 comment)
__global__ __launch_bounds__(BLK, 4) __cluster_dims__(KSPLIT, 1, 1)
void awpinn_fused(
    const float* __restrict__ x, const float* __restrict__ y, const float* __restrict__ z,
    const float* __restrict__ wx, const float* __restrict__ bx,
    const float* __restrict__ wy, const float* __restrict__ by,
    const float* __restrict__ wz, const float* __restrict__ bz,
    const float* __restrict__ coeff, const float* __restrict__ bias,
    float* __restrict__ out, int N)
{
    __shared__ float4 kc[KPB][7];
    __shared__ float  part[4 * PPB];     // this split's partials: [slot][PPB], 8KB

    uint32_t rank;
    asm("mov.u32 %0, %%cluster_ctarank;" : "=r"(rank));
    const int split = (int)rank;                    // 0..7
    const int pg    = blockIdx.x >> 3;              // point-group index
    const int kbase = split * KPB;

    for (int kp = threadIdx.x; kp < KPB; kp += BLK) {
        int k0 = 2 * (kbase + kp), k1 = k0 + 1;
        float wx0 = wx[k0], wx1 = wx[k1];
        float wy0 = wy[k0], wy1 = wy[k1];
        float wz0 = wz[k0], wz1 = wz[k1];
        float c0 = sqrtf(fmaxf(wx0 * wy0 * wz0, 1e-12f)) * coeff[k0];
        float c1 = sqrtf(fmaxf(wx1 * wy1 * wz1, 1e-12f)) * coeff[k1];
        // cp = (-c)*q*exp2(s*C)  ->  sign(-c) XOR ( q * exp2(s*C + log2|c|) )
        float lc0 = __log2f(fabsf(c0));
        float lc1 = __log2f(fabsf(c1));
        unsigned int sg0 = (c0 > 0.0f) ? 0x80000000u : 0u;
        unsigned int sg1 = (c1 > 0.0f) ? 0x80000000u : 0u;
        float wx20 = wx0 * wx0, wx21 = wx1 * wx1;
        float wy20 = wy0 * wy0, wy21 = wy1 * wy1;
        float wz20 = wz0 * wz0, wz21 = wz1 * wz1;
        kc[kp][0] = make_float4(wx0, wx1, -bx[k0], -bx[k1]);
        kc[kp][1] = make_float4(wy0, wy1, -by[k0], -by[k1]);
        kc[kp][2] = make_float4(wz0, wz1, -bz[k0], -bz[k1]);
        kc[kp][3] = make_float4(lc0, lc1, __uint_as_float(sg0), __uint_as_float(sg1));
        kc[kp][4] = make_float4(wx20, wx21, -3.0f * wx20, -3.0f * wx21);
        kc[kp][5] = make_float4(wy20, wy21, -3.0f * wy20, -3.0f * wy21);
        kc[kp][6] = make_float4(wz20, wz21, -3.0f * wz20, -3.0f * wz21);
    }
    __syncthreads();

    const int p0 = pg * PPB + threadIdx.x;

    u64 xd[NPT], yd[NPT], zd[NPT];
    u64 a0[NPT], axx[NPT], ayy[NPT], azz[NPT];

    #pragma unroll
    for (int i = 0; i < NPT; i++) {
        int n = p0 + i * BLK;
        bool ok = (n < N);
        float xv = ok ? x[n] : 0.0f;
        float yv = ok ? y[n] : 0.0f;
        float zv = ok ? z[n] : 0.0f;
        xd[i] = pk2(xv, xv);
        yd[i] = pk2(yv, yv);
        zd[i] = pk2(zv, zv);
        a0[i] = 0ull; axx[i] = 0ull; ayy[i] = 0ull; azz[i] = 0ull;
    }

    const float NEG_HALF_LOG2E = -0.7213475204444817f;
    const u64 Cd = pk2(NEG_HALF_LOG2E, NEG_HALF_LOG2E);

    for (int kp = 0; kp < KPB; kp++) {
        const ulonglong2* p = reinterpret_cast<const ulonglong2*>(&kc[kp][0]);
        const ulonglong2 q0 = p[0];   // {wxp, mbx}
        const ulonglong2 q1 = p[1];   // {wyp, mby}
        const ulonglong2 q2 = p[2];   // {wzp, mbz}
        const ulonglong2 q3 = p[3];   // {lcp, sgn}
        const ulonglong2 q4 = p[4];   // {wx2, m3wx2}
        const ulonglong2 q5 = p[5];   // {wy2, m3wy2}
        const ulonglong2 q6 = p[6];   // {wz2, m3wz2}

        #pragma unroll
        for (int i = 0; i < NPT; i++) {
            u64 xt = fma2(xd[i], q0.x, q0.y);
            u64 yt = fma2(yd[i], q1.x, q1.y);
            u64 zt = fma2(zd[i], q2.x, q2.y);

            u64 x2 = mul2(xt, xt);
            u64 y2 = mul2(yt, yt);
            u64 z2 = mul2(zt, zt);

            u64 s   = add2(add2(x2, y2), z2);
            u64 arg = fma2(s, Cd, q3.x);          // s*C + log2|c|

            float alo, ahi;
            upk2(arg, alo, ahi);
            u64 e = pk2(ex2f(alo), ex2f(ahi));

            u64 q  = mul2(mul2(xt, yt), zt);      // xt*yt*zt
            u64 pe = mul2(q, e);
            u64 cp = pe ^ q3.y;                   // sign of -c (ALU pipe)

            a0[i]  = add2(a0[i], cp);
            axx[i] = fma2(cp, fma2(q4.x, x2, q4.y), axx[i]);
            ayy[i] = fma2(cp, fma2(q5.x, y2, q5.y), ayy[i]);
            azz[i] = fma2(cp, fma2(q6.x, z2, q6.y), azz[i]);
        }
    }

    // ---- store this split's partials to own SMEM ----
    #pragma unroll
    for (int i = 0; i < NPT; i++) {
        int il = threadIdx.x + i * BLK;          // 0..PPB-1
        float lo, hi;
        upk2(a0[i], lo, hi);  part[il]           = lo + hi;
        upk2(axx[i], lo, hi); part[PPB + il]     = lo + hi;
        upk2(ayy[i], lo, hi); part[2 * PPB + il] = lo + hi;
        upk2(azz[i], lo, hi); part[3 * PPB + il] = lo + hi;
    }

    // ---- cluster barrier: all 8 splits' partials visible ----
    asm volatile("barrier.cluster.arrive.aligned;" ::: "memory");
    asm volatile("barrier.cluster.wait.aligned;"   ::: "memory");

    // ---- each CTA finalizes 1/8 of this point-group's outputs ----
    // 4 slots x 512 points = 1024 float2 units; unit u = rank*128 + tid.
    {
        const uint32_t pbase = smem_u32(part);
        int u = split * BLK + threadIdx.x;       // 0..1023
        uint32_t off = pbase + (uint32_t)u * 8u;

        float sx = 0.0f, sy = 0.0f;
        #pragma unroll
        for (int k = 0; k < KSPLIT; k++) {
            uint32_t ra;
            asm("mapa.shared::cluster.u32 %0, %1, %2;" : "=r"(ra) : "r"(off), "r"(k));
            float a, b;
            asm("ld.shared::cluster.v2.f32 {%0, %1}, [%2];"
                : "=f"(a), "=f"(b) : "r"(ra));
            sx += a; sy += b;
        }

        int slot = u >> 8;                        // 256 float2 per slot
        int i2   = u & 255;
        if (slot == 0) {
            float b = bias[0];
            sx += b; sy += b;
        }
        int n = pg * PPB + i2 * 2;
        if (n + 1 < N) {
            *reinterpret_cast<float2*>(&out[slot * N + n]) = make_float2(sx, sy);
        } else if (n < N) {
            out[slot * N + n] = sx;
        }
    }

    // ---- exit barrier: no CTA leaves while peers may still read its SMEM ----
    asm volatile("barrier.cluster.arrive.aligned;" ::: "memory");
    asm volatile("barrier.cluster.wait.aligned;"   ::: "memory");
}

extern "C" void kernel_launch(void* const* d_in, const int* in_sizes, int n_in,
                              void* d_out, int out_size)
{
    const float* x     = (const float*)d_in[0];
    const float* y     = (const float*)d_in[1];
    const float* z     = (const float*)d_in[2];
    const float* wx    = (const float*)d_in[3];
    const float* bx    = (const float*)d_in[4];
    const float* wy    = (const float*)d_in[5];
    const float* by    = (const float*)d_in[6];
    const float* wz    = (const float*)d_in[7];
    const float* bz    = (const float*)d_in[8];
    const float* coeff = (const float*)d_in[9];
    const float* bias  = (const float*)d_in[10];
    float* out = (float*)d_out;

    int N = in_sizes[0];
    int pgroups = (N + PPB - 1) / PPB;
    int grid = pgroups * KSPLIT;     // divisible by cluster size 8

    awpinn_fused<<<grid, BLK>>>(x, y, z, wx, bx, wy, by, wz, bz, coeff, bias, out, N);
}

// round 12
// speedup vs baseline: 1.0512x; 1.0512x over previous
#include <cuda_runtime.h>

#define KW     512
#define KP     (KW / 2)      // k-pairs total
#define KSPLIT 8
#define KPB    (KP / KSPLIT) // k-pairs per block = 32
#define NPT    2             // points per thread
#define BLK    256           // threads per block
#define MAXN   65536

typedef unsigned long long u64;

// scratch[split][slot][n] : KSPLIT splits x 4 output slots x MAXN floats
__device__ float4 g_scratch4[KSPLIT * MAXN];   // = KSPLIT * 4*MAXN floats

// ---------- packed f32x2 helpers ----------
__device__ __forceinline__ u64 pk2(float lo, float hi) {
    u64 r;
    asm("mov.b64 %0, {%1, %2};" : "=l"(r) : "f"(lo), "f"(hi));
    return r;
}
__device__ __forceinline__ void upk2(u64 v, float& lo, float& hi) {
    asm("mov.b64 {%0, %1}, %2;" : "=f"(lo), "=f"(hi) : "l"(v));
}
__device__ __forceinline__ u64 fma2(u64 a, u64 b, u64 c) {
    u64 d;
    asm("fma.rn.f32x2 %0, %1, %2, %3;" : "=l"(d) : "l"(a), "l"(b), "l"(c));
    return d;
}
__device__ __forceinline__ u64 mul2(u64 a, u64 b) {
    u64 d;
    asm("mul.rn.f32x2 %0, %1, %2;" : "=l"(d) : "l"(a), "l"(b));
    return d;
}
__device__ __forceinline__ u64 add2(u64 a, u64 b) {
    u64 d;
    asm("add.rn.f32x2 %0, %1, %2;" : "=l"(d) : "l"(a), "l"(b));
    return d;
}
__device__ __forceinline__ float ex2f(float a) {
    float r;
    asm("ex2.approx.ftz.f32 %0, %1;" : "=f"(r) : "f"(a));
    return r;
}

// Per k-pair constants, 7 x 16B (layout per round-3 comment)
__global__ __launch_bounds__(BLK, 3)
void awpinn_main(
    const float* __restrict__ x, const float* __restrict__ y, const float* __restrict__ z,
    const float* __restrict__ wx, const float* __restrict__ bx,
    const float* __restrict__ wy, const float* __restrict__ by,
    const float* __restrict__ wz, const float* __restrict__ bz,
    const float* __restrict__ coeff, int N)
{
    __shared__ float4 kc[KPB][7];

    const int split = blockIdx.x & (KSPLIT - 1);
    const int pg    = blockIdx.x >> 3;          // point-group index
    const int kbase = split * KPB;              // first k-pair for this block

    for (int kp = threadIdx.x; kp < KPB; kp += BLK) {
        int k0 = 2 * (kbase + kp), k1 = k0 + 1;
        float wx0 = wx[k0], wx1 = wx[k1];
        float wy0 = wy[k0], wy1 = wy[k1];
        float wz0 = wz[k0], wz1 = wz[k1];
        float c0 = sqrtf(fmaxf(wx0 * wy0 * wz0, 1e-12f)) * coeff[k0];
        float c1 = sqrtf(fmaxf(wx1 * wy1 * wz1, 1e-12f)) * coeff[k1];
        // cp = (-c)*q*exp2(s*C)  ->  sign(-c) XOR ( q * exp2(s*C + log2|c|) )
        float lc0 = __log2f(fabsf(c0));
        float lc1 = __log2f(fabsf(c1));
        unsigned int sg0 = (c0 > 0.0f) ? 0x80000000u : 0u;
        unsigned int sg1 = (c1 > 0.0f) ? 0x80000000u : 0u;
        float wx20 = wx0 * wx0, wx21 = wx1 * wx1;
        float wy20 = wy0 * wy0, wy21 = wy1 * wy1;
        float wz20 = wz0 * wz0, wz21 = wz1 * wz1;
        kc[kp][0] = make_float4(wx0, wx1, -bx[k0], -bx[k1]);
        kc[kp][1] = make_float4(wy0, wy1, -by[k0], -by[k1]);
        kc[kp][2] = make_float4(wz0, wz1, -bz[k0], -bz[k1]);
        kc[kp][3] = make_float4(lc0, lc1, __uint_as_float(sg0), __uint_as_float(sg1));
        kc[kp][4] = make_float4(wx20, wx21, -3.0f * wx20, -3.0f * wx21);
        kc[kp][5] = make_float4(wy20, wy21, -3.0f * wy20, -3.0f * wy21);
        kc[kp][6] = make_float4(wz20, wz21, -3.0f * wz20, -3.0f * wz21);
    }
    __syncthreads();

    const int p0 = pg * (BLK * NPT) + threadIdx.x;

    u64 xd[NPT], yd[NPT], zd[NPT];
    u64 a0[NPT], axx[NPT], ayy[NPT], azz[NPT];

    #pragma unroll
    for (int i = 0; i < NPT; i++) {
        int n = p0 + i * BLK;
        bool ok = (n < N);
        float xv = ok ? x[n] : 0.0f;
        float yv = ok ? y[n] : 0.0f;
        float zv = ok ? z[n] : 0.0f;
        xd[i] = pk2(xv, xv);
        yd[i] = pk2(yv, yv);
        zd[i] = pk2(zv, zv);
        a0[i] = 0ull; axx[i] = 0ull; ayy[i] = 0ull; azz[i] = 0ull;
    }

    const float NEG_HALF_LOG2E = -0.7213475204444817f;
    const u64 Cd = pk2(NEG_HALF_LOG2E, NEG_HALF_LOG2E);

    #pragma unroll 2
    for (int kp = 0; kp < KPB; kp++) {
        const ulonglong2* p = reinterpret_cast<const ulonglong2*>(&kc[kp][0]);
        const ulonglong2 q0 = p[0];   // {wxp, mbx}
        const ulonglong2 q1 = p[1];   // {wyp, mby}
        const ulonglong2 q2 = p[2];   // {wzp, mbz}
        const ulonglong2 q3 = p[3];   // {lcp, sgn}
        const ulonglong2 q4 = p[4];   // {wx2, m3wx2}
        const ulonglong2 q5 = p[5];   // {wy2, m3wy2}
        const ulonglong2 q6 = p[6];   // {wz2, m3wz2}

        #pragma unroll
        for (int i = 0; i < NPT; i++) {
            u64 xt = fma2(xd[i], q0.x, q0.y);
            u64 yt = fma2(yd[i], q1.x, q1.y);
            u64 zt = fma2(zd[i], q2.x, q2.y);

            u64 x2 = mul2(xt, xt);
            u64 y2 = mul2(yt, yt);
            u64 z2 = mul2(zt, zt);

            u64 s   = add2(add2(x2, y2), z2);
            u64 arg = fma2(s, Cd, q3.x);          // s*C + log2|c|

            float alo, ahi;
            upk2(arg, alo, ahi);
            u64 e = pk2(ex2f(alo), ex2f(ahi));

            u64 q  = mul2(mul2(xt, yt), zt);      // xt*yt*zt
            u64 pe = mul2(q, e);
            u64 cp = pe ^ q3.y;                   // sign of -c (ALU pipe)

            a0[i]  = add2(a0[i], cp);
            axx[i] = fma2(cp, fma2(q4.x, x2, q4.y), axx[i]);
            ayy[i] = fma2(cp, fma2(q5.x, y2, q5.y), ayy[i]);
            azz[i] = fma2(cp, fma2(q6.x, z2, q6.y), azz[i]);
        }
    }

    float* scr = reinterpret_cast<float*>(g_scratch4) + split * (4 * MAXN);
    #pragma unroll
    for (int i = 0; i < NPT; i++) {
        int n = p0 + i * BLK;
        if (n < N) {
            float lo, hi;
            upk2(a0[i], lo, hi);  scr[n]            = lo + hi;
            upk2(axx[i], lo, hi); scr[MAXN + n]     = lo + hi;
            upk2(ayy[i], lo, hi); scr[2 * MAXN + n] = lo + hi;
            upk2(azz[i], lo, hi); scr[3 * MAXN + n] = lo + hi;
        }
    }
}

// out is 4 rows of N floats, processed in float2 units.
__global__ __launch_bounds__(128)
void awpinn_reduce(const float* __restrict__ bias, float2* __restrict__ out, int N)
{
    const float2* scr2 = reinterpret_cast<const float2*>(g_scratch4);
    int j = blockIdx.x * 128 + threadIdx.x;     // float2 index over 4N floats
    int total = 2 * N;
    if (j < total) {
        int half = N >> 1;                      // float2 per output row
        int slot = j / half;                    // 0..3
        int n2   = j - slot * half;
        const float2* base = scr2 + slot * (MAXN >> 1) + n2;

        float2 v[KSPLIT];
        #pragma unroll
        for (int k = 0; k < KSPLIT; k++)
            v[k] = base[k * (2 * MAXN)];

        float sx = (v[0].x + v[1].x) + (v[2].x + v[3].x);
        float sy = (v[0].y + v[1].y) + (v[2].y + v[3].y);
        sx += (v[4].x + v[5].x) + (v[6].x + v[7].x);
        sy += (v[4].y + v[5].y) + (v[6].y + v[7].y);

        if (slot == 0) {
            float b = bias[0];
            sx += b; sy += b;
        }
        out[j] = make_float2(sx, sy);
    }
}

extern "C" void kernel_launch(void* const* d_in, const int* in_sizes, int n_in,
                              void* d_out, int out_size)
{
    const float* x     = (const float*)d_in[0];
    const float* y     = (const float*)d_in[1];
    const float* z     = (const float*)d_in[2];
    const float* wx    = (const float*)d_in[3];
    const float* bx    = (const float*)d_in[4];
    const float* wy    = (const float*)d_in[5];
    const float* by    = (const float*)d_in[6];
    const float* wz    = (const float*)d_in[7];
    const float* bz    = (const float*)d_in[8];
    const float* coeff = (const float*)d_in[9];
    const float* bias  = (const float*)d_in[10];
    float* out = (float*)d_out;

    int N = in_sizes[0];
    int pts_per_block = BLK * NPT;
    int pgroups = (N + pts_per_block - 1) / pts_per_block;
    int grid = pgroups * KSPLIT;

    awpinn_main<<<grid, BLK>>>(x, y, z, wx, bx, wy, by, wz, bz, coeff, N);
    awpinn_reduce<<<(2 * N + 127) / 128, 128>>>(bias, (float2*)out, N);
}

// round 13
// speedup vs baseline: 1.1033x; 1.0496x over previous
#include <cuda_runtime.h>

#define KW     512
#define KP     (KW / 2)      // k-pairs total
#define KSPLIT 8
#define KPB    (KP / KSPLIT) // k-pairs per block = 32
#define NPT    4             // points per thread
#define BLK    128           // threads per block

typedef unsigned long long u64;

// ---------- packed f32x2 helpers ----------
__device__ __forceinline__ u64 pk2(float lo, float hi) {
    u64 r;
    asm("mov.b64 %0, {%1, %2};" : "=l"(r) : "f"(lo), "f"(hi));
    return r;
}
__device__ __forceinline__ void upk2(u64 v, float& lo, float& hi) {
    asm("mov.b64 {%0, %1}, %2;" : "=f"(lo), "=f"(hi) : "l"(v));
}
__device__ __forceinline__ u64 fma2(u64 a, u64 b, u64 c) {
    u64 d;
    asm("fma.rn.f32x2 %0, %1, %2, %3;" : "=l"(d) : "l"(a), "l"(b), "l"(c));
    return d;
}
__device__ __forceinline__ u64 mul2(u64 a, u64 b) {
    u64 d;
    asm("mul.rn.f32x2 %0, %1, %2;" : "=l"(d) : "l"(a), "l"(b));
    return d;
}
__device__ __forceinline__ u64 add2(u64 a, u64 b) {
    u64 d;
    asm("add.rn.f32x2 %0, %1, %2;" : "=l"(d) : "l"(a), "l"(b));
    return d;
}
__device__ __forceinline__ float ex2f(float a) {
    float r;
    asm("ex2.approx.ftz.f32 %0, %1;" : "=f"(r) : "f"(a));
    return r;
}

// Init: out[0..N) = bias, out[N..4N) = 0   (out is poisoned before timing)
__global__ __launch_bounds__(256)
void awpinn_init(const float* __restrict__ bias, float* __restrict__ out, int N)
{
    int j = blockIdx.x * 256 + threadIdx.x;
    float b = bias[0];
    if (j < 4 * N)
        out[j] = (j < N) ? b : 0.0f;
}

// Per k-pair constants, 7 x 16B (layout per round-3 comment)
__global__ __launch_bounds__(BLK, 4)
void awpinn_main(
    const float* __restrict__ x, const float* __restrict__ y, const float* __restrict__ z,
    const float* __restrict__ wx, const float* __restrict__ bx,
    const float* __restrict__ wy, const float* __restrict__ by,
    const float* __restrict__ wz, const float* __restrict__ bz,
    const float* __restrict__ coeff, float* __restrict__ out, int N)
{
    __shared__ float4 kc[KPB][7];

    const int split = blockIdx.x & (KSPLIT - 1);
    const int pg    = blockIdx.x >> 3;          // point-group index
    const int kbase = split * KPB;              // first k-pair for this block

    for (int kp = threadIdx.x; kp < KPB; kp += BLK) {
        int k0 = 2 * (kbase + kp), k1 = k0 + 1;
        float wx0 = wx[k0], wx1 = wx[k1];
        float wy0 = wy[k0], wy1 = wy[k1];
        float wz0 = wz[k0], wz1 = wz[k1];
        float c0 = sqrtf(fmaxf(wx0 * wy0 * wz0, 1e-12f)) * coeff[k0];
        float c1 = sqrtf(fmaxf(wx1 * wy1 * wz1, 1e-12f)) * coeff[k1];
        // cp = (-c)*q*exp2(s*C)  ->  sign(-c) XOR ( q * exp2(s*C + log2|c|) )
        float lc0 = __log2f(fabsf(c0));
        float lc1 = __log2f(fabsf(c1));
        unsigned int sg0 = (c0 > 0.0f) ? 0x80000000u : 0u;
        unsigned int sg1 = (c1 > 0.0f) ? 0x80000000u : 0u;
        float wx20 = wx0 * wx0, wx21 = wx1 * wx1;
        float wy20 = wy0 * wy0, wy21 = wy1 * wy1;
        float wz20 = wz0 * wz0, wz21 = wz1 * wz1;
        kc[kp][0] = make_float4(wx0, wx1, -bx[k0], -bx[k1]);
        kc[kp][1] = make_float4(wy0, wy1, -by[k0], -by[k1]);
        kc[kp][2] = make_float4(wz0, wz1, -bz[k0], -bz[k1]);
        kc[kp][3] = make_float4(lc0, lc1, __uint_as_float(sg0), __uint_as_float(sg1));
        kc[kp][4] = make_float4(wx20, wx21, -3.0f * wx20, -3.0f * wx21);
        kc[kp][5] = make_float4(wy20, wy21, -3.0f * wy20, -3.0f * wy21);
        kc[kp][6] = make_float4(wz20, wz21, -3.0f * wz20, -3.0f * wz21);
    }
    __syncthreads();

    const int p0 = pg * (BLK * NPT) + threadIdx.x;

    u64 xd[NPT], yd[NPT], zd[NPT];
    u64 a0[NPT], axx[NPT], ayy[NPT], azz[NPT];

    #pragma unroll
    for (int i = 0; i < NPT; i++) {
        int n = p0 + i * BLK;
        bool ok = (n < N);
        float xv = ok ? x[n] : 0.0f;
        float yv = ok ? y[n] : 0.0f;
        float zv = ok ? z[n] : 0.0f;
        xd[i] = pk2(xv, xv);
        yd[i] = pk2(yv, yv);
        zd[i] = pk2(zv, zv);
        a0[i] = 0ull; axx[i] = 0ull; ayy[i] = 0ull; azz[i] = 0ull;
    }

    const float NEG_HALF_LOG2E = -0.7213475204444817f;
    const u64 Cd = pk2(NEG_HALF_LOG2E, NEG_HALF_LOG2E);

    for (int kp = 0; kp < KPB; kp++) {
        const ulonglong2* p = reinterpret_cast<const ulonglong2*>(&kc[kp][0]);
        const ulonglong2 q0 = p[0];   // {wxp, mbx}
        const ulonglong2 q1 = p[1];   // {wyp, mby}
        const ulonglong2 q2 = p[2];   // {wzp, mbz}
        const ulonglong2 q3 = p[3];   // {lcp, sgn}
        const ulonglong2 q4 = p[4];   // {wx2, m3wx2}
        const ulonglong2 q5 = p[5];   // {wy2, m3wy2}
        const ulonglong2 q6 = p[6];   // {wz2, m3wz2}

        #pragma unroll
        for (int i = 0; i < NPT; i++) {
            u64 xt = fma2(xd[i], q0.x, q0.y);
            u64 yt = fma2(yd[i], q1.x, q1.y);
            u64 zt = fma2(zd[i], q2.x, q2.y);

            u64 x2 = mul2(xt, xt);
            u64 y2 = mul2(yt, yt);
            u64 z2 = mul2(zt, zt);

            u64 s   = add2(add2(x2, y2), z2);
            u64 arg = fma2(s, Cd, q3.x);          // s*C + log2|c|

            float alo, ahi;
            upk2(arg, alo, ahi);
            u64 e = pk2(ex2f(alo), ex2f(ahi));

            u64 q  = mul2(mul2(xt, yt), zt);      // xt*yt*zt
            u64 pe = mul2(q, e);
            u64 cp = pe ^ q3.y;                   // sign of -c (ALU pipe)

            a0[i]  = add2(a0[i], cp);
            axx[i] = fma2(cp, fma2(q4.x, x2, q4.y), axx[i]);
            ayy[i] = fma2(cp, fma2(q5.x, y2, q5.y), ayy[i]);
            azz[i] = fma2(cp, fma2(q6.x, z2, q6.y), azz[i]);
        }
    }

    // ---- reduce across splits directly into out via RED.ADD (no return) ----
    #pragma unroll
    for (int i = 0; i < NPT; i++) {
        int n = p0 + i * BLK;
        if (n < N) {
            float lo, hi;
            upk2(a0[i], lo, hi);  atomicAdd(&out[n],         lo + hi);
            upk2(axx[i], lo, hi); atomicAdd(&out[N + n],     lo + hi);
            upk2(ayy[i], lo, hi); atomicAdd(&out[2 * N + n], lo + hi);
            upk2(azz[i], lo, hi); atomicAdd(&out[3 * N + n], lo + hi);
        }
    }
}

extern "C" void kernel_launch(void* const* d_in, const int* in_sizes, int n_in,
                              void* d_out, int out_size)
{
    const float* x     = (const float*)d_in[0];
    const float* y     = (const float*)d_in[1];
    const float* z     = (const float*)d_in[2];
    const float* wx    = (const float*)d_in[3];
    const float* bx    = (const float*)d_in[4];
    const float* wy    = (const float*)d_in[5];
    const float* by    = (const float*)d_in[6];
    const float* wz    = (const float*)d_in[7];
    const float* bz    = (const float*)d_in[8];
    const float* coeff = (const float*)d_in[9];
    const float* bias  = (const float*)d_in[10];
    float* out = (float*)d_out;

    int N = in_sizes[0];
    int pts_per_block = BLK * NPT;
    int pgroups = (N + pts_per_block - 1) / pts_per_block;
    int grid = pgroups * KSPLIT;

    awpinn_init<<<(4 * N + 255) / 256, 256>>>(bias, out, N);
    awpinn_main<<<grid, BLK>>>(x, y, z, wx, bx, wy, by, wz, bz, coeff, out, N);
}

// round 14
// speedup vs baseline: 1.1090x; 1.0051x over previous
#include <cuda_runtime.h>

#define KW     512
#define KP     (KW / 2)      // k-pairs total
#define KSPLIT 8
#define KPB    (KP / KSPLIT) // k-pairs per block = 32
#define NPT    4             // points per thread (2 adjacent pairs)
#define BLK    128           // threads per block
#define PPB    (BLK * NPT)   // 512 points per point-group

typedef unsigned long long u64;

// ---------- packed f32x2 helpers ----------
__device__ __forceinline__ u64 pk2(float lo, float hi) {
    u64 r;
    asm("mov.b64 %0, {%1, %2};" : "=l"(r) : "f"(lo), "f"(hi));
    return r;
}
__device__ __forceinline__ void upk2(u64 v, float& lo, float& hi) {
    asm("mov.b64 {%0, %1}, %2;" : "=f"(lo), "=f"(hi) : "l"(v));
}
__device__ __forceinline__ u64 fma2(u64 a, u64 b, u64 c) {
    u64 d;
    asm("fma.rn.f32x2 %0, %1, %2, %3;" : "=l"(d) : "l"(a), "l"(b), "l"(c));
    return d;
}
__device__ __forceinline__ u64 mul2(u64 a, u64 b) {
    u64 d;
    asm("mul.rn.f32x2 %0, %1, %2;" : "=l"(d) : "l"(a), "l"(b));
    return d;
}
__device__ __forceinline__ u64 add2(u64 a, u64 b) {
    u64 d;
    asm("add.rn.f32x2 %0, %1, %2;" : "=l"(d) : "l"(a), "l"(b));
    return d;
}
__device__ __forceinline__ float ex2f(float a) {
    float r;
    asm("ex2.approx.ftz.f32 %0, %1;" : "=f"(r) : "f"(a));
    return r;
}
__device__ __forceinline__ void red_add_v2(float* p, float a, float b) {
    asm volatile("red.global.add.v2.f32 [%0], {%1, %2};"
                 :: "l"(p), "f"(a), "f"(b) : "memory");
}

// Init: out[0..N) = bias, out[N..4N) = 0   (out is poisoned before timing)
__global__ __launch_bounds__(256)
void awpinn_init(const float* __restrict__ bias, float4* __restrict__ out, int N)
{
    int j = blockIdx.x * 256 + threadIdx.x;    // float4 units over 4N floats
    int total = N;                              // 4N/4
    int row0  = N >> 2;                         // float4 units in row 0
    if (j < total) {
        float b = (j < row0) ? bias[0] : 0.0f;
        out[j] = make_float4(b, b, b, b);
    }
}

// Per k-pair constants, 7 x 16B (layout per round-3 comment)
__global__ __launch_bounds__(BLK, 4)
void awpinn_main(
    const float* __restrict__ x, const float* __restrict__ y, const float* __restrict__ z,
    const float* __restrict__ wx, const float* __restrict__ bx,
    const float* __restrict__ wy, const float* __restrict__ by,
    const float* __restrict__ wz, const float* __restrict__ bz,
    const float* __restrict__ coeff, float* __restrict__ out, int N)
{
    __shared__ float4 kc[KPB][7];

    const int split = blockIdx.x & (KSPLIT - 1);
    const int pg    = blockIdx.x >> 3;          // point-group index
    const int kbase = split * KPB;              // first k-pair for this block

    for (int kp = threadIdx.x; kp < KPB; kp += BLK) {
        int k0 = 2 * (kbase + kp), k1 = k0 + 1;
        float wx0 = wx[k0], wx1 = wx[k1];
        float wy0 = wy[k0], wy1 = wy[k1];
        float wz0 = wz[k0], wz1 = wz[k1];
        float c0 = sqrtf(fmaxf(wx0 * wy0 * wz0, 1e-12f)) * coeff[k0];
        float c1 = sqrtf(fmaxf(wx1 * wy1 * wz1, 1e-12f)) * coeff[k1];
        // cp = (-c)*q*exp2(s*C)  ->  sign(-c) XOR ( q * exp2(s*C + log2|c|) )
        float lc0 = __log2f(fabsf(c0));
        float lc1 = __log2f(fabsf(c1));
        unsigned int sg0 = (c0 > 0.0f) ? 0x80000000u : 0u;
        unsigned int sg1 = (c1 > 0.0f) ? 0x80000000u : 0u;
        float wx20 = wx0 * wx0, wx21 = wx1 * wx1;
        float wy20 = wy0 * wy0, wy21 = wy1 * wy1;
        float wz20 = wz0 * wz0, wz21 = wz1 * wz1;
        kc[kp][0] = make_float4(wx0, wx1, -bx[k0], -bx[k1]);
        kc[kp][1] = make_float4(wy0, wy1, -by[k0], -by[k1]);
        kc[kp][2] = make_float4(wz0, wz1, -bz[k0], -bz[k1]);
        kc[kp][3] = make_float4(lc0, lc1, __uint_as_float(sg0), __uint_as_float(sg1));
        kc[kp][4] = make_float4(wx20, wx21, -3.0f * wx20, -3.0f * wx21);
        kc[kp][5] = make_float4(wy20, wy21, -3.0f * wy20, -3.0f * wy21);
        kc[kp][6] = make_float4(wz20, wz21, -3.0f * wz20, -3.0f * wz21);
    }
    __syncthreads();

    // Pairwise point mapping: pair j (j=0,1) covers points
    //   n(j) = pg*PPB + j*(PPB/2) + 2*tid + {0,1}
    // i = 2*j + e, e in {0,1}: thread's points 2j, 2j+1 are ADJACENT in memory.
    const int nb0 = pg * PPB + 2 * threadIdx.x;          // pair 0 even point
    const int nb1 = nb0 + (PPB / 2);                     // pair 1 even point

    u64 xd[NPT], yd[NPT], zd[NPT];
    u64 a0[NPT], axx[NPT], ayy[NPT], azz[NPT];

    #pragma unroll
    for (int j = 0; j < 2; j++) {
        int n = (j == 0) ? nb0 : nb1;
        float2 xv = make_float2(0.0f, 0.0f), yv = xv, zv = xv;
        if (n + 1 < N) {
            xv = *reinterpret_cast<const float2*>(&x[n]);
            yv = *reinterpret_cast<const float2*>(&y[n]);
            zv = *reinterpret_cast<const float2*>(&z[n]);
        } else if (n < N) {
            xv.x = x[n]; yv.x = y[n]; zv.x = z[n];
        }
        xd[2*j]   = pk2(xv.x, xv.x);
        xd[2*j+1] = pk2(xv.y, xv.y);
        yd[2*j]   = pk2(yv.x, yv.x);
        yd[2*j+1] = pk2(yv.y, yv.y);
        zd[2*j]   = pk2(zv.x, zv.x);
        zd[2*j+1] = pk2(zv.y, zv.y);
    }
    #pragma unroll
    for (int i = 0; i < NPT; i++) {
        a0[i] = 0ull; axx[i] = 0ull; ayy[i] = 0ull; azz[i] = 0ull;
    }

    const float NEG_HALF_LOG2E = -0.7213475204444817f;
    const u64 Cd = pk2(NEG_HALF_LOG2E, NEG_HALF_LOG2E);

    for (int kp = 0; kp < KPB; kp++) {
        const ulonglong2* p = reinterpret_cast<const ulonglong2*>(&kc[kp][0]);
        const ulonglong2 q0 = p[0];   // {wxp, mbx}
        const ulonglong2 q1 = p[1];   // {wyp, mby}
        const ulonglong2 q2 = p[2];   // {wzp, mbz}
        const ulonglong2 q3 = p[3];   // {lcp, sgn}
        const ulonglong2 q4 = p[4];   // {wx2, m3wx2}
        const ulonglong2 q5 = p[5];   // {wy2, m3wy2}
        const ulonglong2 q6 = p[6];   // {wz2, m3wz2}

        #pragma unroll
        for (int i = 0; i < NPT; i++) {
            u64 xt = fma2(xd[i], q0.x, q0.y);
            u64 yt = fma2(yd[i], q1.x, q1.y);
            u64 zt = fma2(zd[i], q2.x, q2.y);

            u64 x2 = mul2(xt, xt);
            u64 y2 = mul2(yt, yt);
            u64 z2 = mul2(zt, zt);

            u64 s   = add2(add2(x2, y2), z2);
            u64 arg = fma2(s, Cd, q3.x);          // s*C + log2|c|

            float alo, ahi;
            upk2(arg, alo, ahi);
            u64 e = pk2(ex2f(alo), ex2f(ahi));

            u64 q  = mul2(mul2(xt, yt), zt);      // xt*yt*zt
            u64 pe = mul2(q, e);
            u64 cp = pe ^ q3.y;                   // sign of -c (ALU pipe)

            a0[i]  = add2(a0[i], cp);
            axx[i] = fma2(cp, fma2(q4.x, x2, q4.y), axx[i]);
            ayy[i] = fma2(cp, fma2(q5.x, y2, q5.y), ayy[i]);
            azz[i] = fma2(cp, fma2(q6.x, z2, q6.y), azz[i]);
        }
    }

    // ---- reduce across splits into out via 8-byte vector RED ----
    #pragma unroll
    for (int j = 0; j < 2; j++) {
        int n = (j == 0) ? nb0 : nb1;
        int i0 = 2 * j, i1 = 2 * j + 1;
        float l0, h0, l1, h1;

        if (n + 1 < N) {
            upk2(a0[i0], l0, h0);  upk2(a0[i1], l1, h1);
            red_add_v2(&out[n],         l0 + h0, l1 + h1);
            upk2(axx[i0], l0, h0); upk2(axx[i1], l1, h1);
            red_add_v2(&out[N + n],     l0 + h0, l1 + h1);
            upk2(ayy[i0], l0, h0); upk2(ayy[i1], l1, h1);
            red_add_v2(&out[2 * N + n], l0 + h0, l1 + h1);
            upk2(azz[i0], l0, h0); upk2(azz[i1], l1, h1);
            red_add_v2(&out[3 * N + n], l0 + h0, l1 + h1);
        } else if (n < N) {
            upk2(a0[i0], l0, h0);  atomicAdd(&out[n],         l0 + h0);
            upk2(axx[i0], l0, h0); atomicAdd(&out[N + n],     l0 + h0);
            upk2(ayy[i0], l0, h0); atomicAdd(&out[2 * N + n], l0 + h0);
            upk2(azz[i0], l0, h0); atomicAdd(&out[3 * N + n], l0 + h0);
        }
    }
}

extern "C" void kernel_launch(void* const* d_in, const int* in_sizes, int n_in,
                              void* d_out, int out_size)
{
    const float* x     = (const float*)d_in[0];
    const float* y     = (const float*)d_in[1];
    const float* z     = (const float*)d_in[2];
    const float* wx    = (const float*)d_in[3];
    const float* bx    = (const float*)d_in[4];
    const float* wy    = (const float*)d_in[5];
    const float* by    = (const float*)d_in[6];
    const float* wz    = (const float*)d_in[7];
    const float* bz    = (const float*)d_in[8];
    const float* coeff = (const float*)d_in[9];
    const float* bias  = (const float*)d_in[10];
    float* out = (float*)d_out;

    int N = in_sizes[0];
    int pgroups = (N + PPB - 1) / PPB;
    int grid = pgroups * KSPLIT;

    awpinn_init<<<(N + 255) / 256, 256>>>(bias, (float4*)out, N);
    awpinn_main<<<grid, BLK>>>(x, y, z, wx, bx, wy, by, wz, bz, coeff, out, N);
}

// round 15
// speedup vs baseline: 1.1320x; 1.0208x over previous
#include <cuda_runtime.h>

#define KW     512
#define KP     (KW / 2)      // k-pairs total
#define KSPLIT 8
#define KPB    (KP / KSPLIT) // k-pairs per block = 32
#define NPT    4             // points per thread
#define BLK    128           // threads per block

typedef unsigned long long u64;

// ---------- packed f32x2 helpers ----------
__device__ __forceinline__ u64 pk2(float lo, float hi) {
    u64 r;
    asm("mov.b64 %0, {%1, %2};" : "=l"(r) : "f"(lo), "f"(hi));
    return r;
}
__device__ __forceinline__ void upk2(u64 v, float& lo, float& hi) {
    asm("mov.b64 {%0, %1}, %2;" : "=f"(lo), "=f"(hi) : "l"(v));
}
__device__ __forceinline__ u64 fma2(u64 a, u64 b, u64 c) {
    u64 d;
    asm("fma.rn.f32x2 %0, %1, %2, %3;" : "=l"(d) : "l"(a), "l"(b), "l"(c));
    return d;
}
__device__ __forceinline__ u64 mul2(u64 a, u64 b) {
    u64 d;
    asm("mul.rn.f32x2 %0, %1, %2;" : "=l"(d) : "l"(a), "l"(b));
    return d;
}
__device__ __forceinline__ u64 add2(u64 a, u64 b) {
    u64 d;
    asm("add.rn.f32x2 %0, %1, %2;" : "=l"(d) : "l"(a), "l"(b));
    return d;
}
__device__ __forceinline__ float ex2f(float a) {
    float r;
    asm("ex2.approx.ftz.f32 %0, %1;" : "=f"(r) : "f"(a));
    return r;
}

// Init: out[0..N) = bias, out[N..4N) = 0, float4 stores (out poisoned before timing)
__global__ __launch_bounds__(256)
void awpinn_init(const float* __restrict__ bias, float4* __restrict__ out, int N)
{
    int j = blockIdx.x * 256 + threadIdx.x;    // float4 units over 4N floats
    int total = N;                              // 4N/4
    int row0  = N >> 2;                         // float4 units in row 0
    if (j < total) {
        float b = (j < row0) ? bias[0] : 0.0f;
        out[j] = make_float4(b, b, b, b);
    }
}

// Per k-pair constants, 7 x 16B (layout per round-3 comment)
__global__ __launch_bounds__(BLK, 4)
void awpinn_main(
    const float* __restrict__ x, const float* __restrict__ y, const float* __restrict__ z,
    const float* __restrict__ wx, const float* __restrict__ bx,
    const float* __restrict__ wy, const float* __restrict__ by,
    const float* __restrict__ wz, const float* __restrict__ bz,
    const float* __restrict__ coeff, float* __restrict__ out, int N)
{
    __shared__ float4 kc[KPB][7];

    const int split = blockIdx.x & (KSPLIT - 1);
    const int pg    = blockIdx.x >> 3;          // point-group index
    const int kbase = split * KPB;              // first k-pair for this block

    for (int kp = threadIdx.x; kp < KPB; kp += BLK) {
        int k0 = 2 * (kbase + kp), k1 = k0 + 1;
        float wx0 = wx[k0], wx1 = wx[k1];
        float wy0 = wy[k0], wy1 = wy[k1];
        float wz0 = wz[k0], wz1 = wz[k1];
        float c0 = sqrtf(fmaxf(wx0 * wy0 * wz0, 1e-12f)) * coeff[k0];
        float c1 = sqrtf(fmaxf(wx1 * wy1 * wz1, 1e-12f)) * coeff[k1];
        // cp = (-c)*q*exp2(s*C)  ->  sign(-c) XOR ( q * exp2(s*C + log2|c|) )
        float lc0 = __log2f(fabsf(c0));
        float lc1 = __log2f(fabsf(c1));
        unsigned int sg0 = (c0 > 0.0f) ? 0x80000000u : 0u;
        unsigned int sg1 = (c1 > 0.0f) ? 0x80000000u : 0u;
        float wx20 = wx0 * wx0, wx21 = wx1 * wx1;
        float wy20 = wy0 * wy0, wy21 = wy1 * wy1;
        float wz20 = wz0 * wz0, wz21 = wz1 * wz1;
        kc[kp][0] = make_float4(wx0, wx1, -bx[k0], -bx[k1]);
        kc[kp][1] = make_float4(wy0, wy1, -by[k0], -by[k1]);
        kc[kp][2] = make_float4(wz0, wz1, -bz[k0], -bz[k1]);
        kc[kp][3] = make_float4(lc0, lc1, __uint_as_float(sg0), __uint_as_float(sg1));
        kc[kp][4] = make_float4(wx20, wx21, -3.0f * wx20, -3.0f * wx21);
        kc[kp][5] = make_float4(wy20, wy21, -3.0f * wy20, -3.0f * wy21);
        kc[kp][6] = make_float4(wz20, wz21, -3.0f * wz20, -3.0f * wz21);
    }
    __syncthreads();

    const int p0 = pg * (BLK * NPT) + threadIdx.x;

    u64 xd[NPT], yd[NPT], zd[NPT];
    u64 a0[NPT], axx[NPT], ayy[NPT], azz[NPT];

    #pragma unroll
    for (int i = 0; i < NPT; i++) {
        int n = p0 + i * BLK;
        bool ok = (n < N);
        float xv = ok ? x[n] : 0.0f;
        float yv = ok ? y[n] : 0.0f;
        float zv = ok ? z[n] : 0.0f;
        xd[i] = pk2(xv, xv);
        yd[i] = pk2(yv, yv);
        zd[i] = pk2(zv, zv);
        a0[i] = 0ull; axx[i] = 0ull; ayy[i] = 0ull; azz[i] = 0ull;
    }

    const float NEG_HALF_LOG2E = -0.7213475204444817f;
    const u64 Cd = pk2(NEG_HALF_LOG2E, NEG_HALF_LOG2E);

    for (int kp = 0; kp < KPB; kp++) {
        const ulonglong2* p = reinterpret_cast<const ulonglong2*>(&kc[kp][0]);
        const ulonglong2 q0 = p[0];   // {wxp, mbx}
        const ulonglong2 q1 = p[1];   // {wyp, mby}
        const ulonglong2 q2 = p[2];   // {wzp, mbz}
        const ulonglong2 q3 = p[3];   // {lcp, sgn}
        const ulonglong2 q4 = p[4];   // {wx2, m3wx2}
        const ulonglong2 q5 = p[5];   // {wy2, m3wy2}
        const ulonglong2 q6 = p[6];   // {wz2, m3wz2}

        #pragma unroll
        for (int i = 0; i < NPT; i++) {
            u64 xt = fma2(xd[i], q0.x, q0.y);
            u64 yt = fma2(yd[i], q1.x, q1.y);
            u64 zt = fma2(zd[i], q2.x, q2.y);

            u64 x2 = mul2(xt, xt);
            u64 y2 = mul2(yt, yt);
            u64 z2 = mul2(zt, zt);

            u64 s   = add2(add2(x2, y2), z2);
            u64 arg = fma2(s, Cd, q3.x);          // s*C + log2|c|

            float alo, ahi;
            upk2(arg, alo, ahi);
            u64 e = pk2(ex2f(alo), ex2f(ahi));

            u64 q  = mul2(mul2(xt, yt), zt);      // xt*yt*zt
            u64 pe = mul2(q, e);
            u64 cp = pe ^ q3.y;                   // sign of -c (ALU pipe)

            a0[i]  = add2(a0[i], cp);
            axx[i] = fma2(cp, fma2(q4.x, x2, q4.y), axx[i]);
            ayy[i] = fma2(cp, fma2(q5.x, y2, q5.y), ayy[i]);
            azz[i] = fma2(cp, fma2(q6.x, z2, q6.y), azz[i]);
        }
    }

    // ---- reduce across splits directly into out via RED.ADD (no return) ----
    #pragma unroll
    for (int i = 0; i < NPT; i++) {
        int n = p0 + i * BLK;
        if (n < N) {
            float lo, hi;
            upk2(a0[i], lo, hi);  atomicAdd(&out[n],         lo + hi);
            upk2(axx[i], lo, hi); atomicAdd(&out[N + n],     lo + hi);
            upk2(ayy[i], lo, hi); atomicAdd(&out[2 * N + n], lo + hi);
            upk2(azz[i], lo, hi); atomicAdd(&out[3 * N + n], lo + hi);
        }
    }
}

extern "C" void kernel_launch(void* const* d_in, const int* in_sizes, int n_in,
                              void* d_out, int out_size)
{
    const float* x     = (const float*)d_in[0];
    const float* y     = (const float*)d_in[1];
    const float* z     = (const float*)d_in[2];
    const float* wx    = (const float*)d_in[3];
    const float* bx    = (const float*)d_in[4];
    const float* wy    = (const float*)d_in[5];
    const float* by    = (const float*)d_in[6];
    const float* wz    = (const float*)d_in[7];
    const float* bz    = (const float*)d_in[8];
    const float* coeff = (const float*)d_in[9];
    const float* bias  = (const float*)d_in[10];
    float* out = (float*)d_out;

    int N = in_sizes[0];
    int pts_per_block = BLK * NPT;
    int pgroups = (N + pts_per_block - 1) / pts_per_block;
    int grid = pgroups * KSPLIT;

    awpinn_init<<<(N + 255) / 256, 256>>>(bias, (float4*)out, N);
    awpinn_main<<<grid, BLK>>>(x, y, z, wx, bx, wy, by, wz, bz, coeff, out, N);
}